// round 8
// baseline (speedup 1.0000x reference)
#include <cuda_runtime.h>
#include <cstdint>

// ---------------------------------------------------------------------------
// Router: r[b,e] = || W[e] @ x[b] ||_2
//   x: [8192, 4096] f32, W: [16, 64, 4096] f32 (row-major), out: [8192,16] f32
// GEMM C[8192,1024] = X @ W^T via legacy mma.sync.m16n8k8.tf32 (base sm_103:
// tcgen05 rejected by this build's ptxas).
// R8 vs R7 (520us, GEMM ~477us): the mainloop was warp-starvation bound
// (2 warps/SMSP, tensor=45%). -> 512 threads / 16 warps (4 per SMSP),
// warp tile 32x64 (4m x 4n warps), acc halves to 64 regs/thread so the
// 128-reg cap of 512-thread CTAs holds. Same tiles, pipeline, prep.
// ---------------------------------------------------------------------------

#define BDIM   8192
#define DDIM   4096
#define EDIM   16
#define NTOT   1024
#define BM     128
#define BN     256
#define BK     32
#define STAGES 3
#define KT     (DDIM / BK)             /* 128 */
#define LDA    (BK + 4)                /* 36 floats; rows 16B-aligned (144B) */
#define A_STG  (BM * LDA)              /* 4608 floats */
#define B_STG  (BN * LDA)              /* 9216 floats */
#define SMEM_BYTES (STAGES * (A_STG + B_STG) * 4)   /* 165888 */

// tf32-rounded scratch copies (module-scope __device__: sanctioned scratch)
__device__ float g_xr[(size_t)BDIM * DDIM];   // 134 MB
__device__ float g_wr[(size_t)NTOT * DDIM];   //  17 MB

__device__ __forceinline__ void mma_tf32(float c[4],
                                         uint32_t a0, uint32_t a1,
                                         uint32_t a2, uint32_t a3,
                                         uint32_t b0, uint32_t b1) {
    asm volatile(
        "mma.sync.aligned.m16n8k8.row.col.f32.tf32.tf32.f32 "
        "{%0,%1,%2,%3}, {%4,%5,%6,%7}, {%8,%9}, {%0,%1,%2,%3};"
        : "+f"(c[0]), "+f"(c[1]), "+f"(c[2]), "+f"(c[3])
        : "r"(a0), "r"(a1), "r"(a2), "r"(a3), "r"(b0), "r"(b1));
}

__device__ __forceinline__ void cp16(uint32_t dst, const float* src) {
    asm volatile("cp.async.cg.shared.global [%0], [%1], 16;"
                 :: "r"(dst), "l"(src) : "memory");
}

__device__ __forceinline__ uint32_t fu(float f) { return __float_as_uint(f); }

// ---------------------------------------------------------------------------
// Prep: round inputs to tf32 (RNA -> unbiased) into scratch
// ---------------------------------------------------------------------------
__global__ void prep_round_x(const float4* __restrict__ src) {
    size_t i = (size_t)blockIdx.x * blockDim.x + threadIdx.x;
    float4 v = src[i];
    uint4 o;
    asm("cvt.rna.tf32.f32 %0, %1;" : "=r"(o.x) : "f"(v.x));
    asm("cvt.rna.tf32.f32 %0, %1;" : "=r"(o.y) : "f"(v.y));
    asm("cvt.rna.tf32.f32 %0, %1;" : "=r"(o.z) : "f"(v.z));
    asm("cvt.rna.tf32.f32 %0, %1;" : "=r"(o.w) : "f"(v.w));
    reinterpret_cast<uint4*>(g_xr)[i] = o;
}

__global__ void prep_round_w(const float4* __restrict__ src) {
    size_t i = (size_t)blockIdx.x * blockDim.x + threadIdx.x;
    float4 v = src[i];
    uint4 o;
    asm("cvt.rna.tf32.f32 %0, %1;" : "=r"(o.x) : "f"(v.x));
    asm("cvt.rna.tf32.f32 %0, %1;" : "=r"(o.y) : "f"(v.y));
    asm("cvt.rna.tf32.f32 %0, %1;" : "=r"(o.z) : "f"(v.z));
    asm("cvt.rna.tf32.f32 %0, %1;" : "=r"(o.w) : "f"(v.w));
    reinterpret_cast<uint4*>(g_wr)[i] = o;
}

// ---------------------------------------------------------------------------
// grid = (NTOT/BN = 4, BDIM/BM = 64); n fastest -> 4 n-tiles of an m-tile
// co-resident (A fetched from DRAM once). 16 warps: 4(m) x 4(n), warp tile
// 32x64 = one expert per warp.
// ---------------------------------------------------------------------------
__global__ __launch_bounds__(512, 1)
void router_kernel(float* __restrict__ out) {
    extern __shared__ float smem[];
    float* As = smem;                       // [STAGES][BM][LDA]
    float* Bs = smem + STAGES * A_STG;      // [STAGES][BN][LDA]

    const int tid  = threadIdx.x;
    const int lane = tid & 31;
    const int wid  = tid >> 5;              // 0..15
    const int wm   = wid & 3;               // 0..3  (m-warp: 32 rows)
    const int wn   = wid >> 2;              // 0..3  (n-warp / expert)

    const int m_base = blockIdx.y * BM;
    const int n_base = blockIdx.x * BN;

    // ---- cp.async producer: thread -> (row = tid/8, 16B chunk = tid%8) ----
    const int lrow = tid >> 3;               // 0..63
    const int lch  = tid & 7;                // 0..7
    const float* gA = g_xr + (size_t)(m_base + lrow) * DDIM + lch * 4;
    const float* gB = g_wr + (size_t)(n_base + lrow) * DDIM + lch * 4;
    const uint32_t sA0 = (uint32_t)__cvta_generic_to_shared(As)
                       + (uint32_t)(lrow * LDA + lch * 4) * 4u;
    const uint32_t sB0 = (uint32_t)__cvta_generic_to_shared(Bs)
                       + (uint32_t)(lrow * LDA + lch * 4) * 4u;

    auto load_stage = [&](int s, int k0) {
        const uint32_t a = sA0 + (uint32_t)(s * A_STG) * 4u;
        const float* ga = gA + k0;
#pragma unroll
        for (int p = 0; p < BM / 64; ++p)                 // 2 passes of 64 rows
            cp16(a + (uint32_t)(p * 64 * LDA) * 4u, ga + (size_t)(p * 64) * DDIM);
        const uint32_t b = sB0 + (uint32_t)(s * B_STG) * 4u;
        const float* gb = gB + k0;
#pragma unroll
        for (int p = 0; p < BN / 64; ++p)                 // 4 passes of 64 rows
            cp16(b + (uint32_t)(p * 64 * LDA) * 4u, gb + (size_t)(p * 64) * DDIM);
    };

#pragma unroll
    for (int s = 0; s < STAGES - 1; ++s) {
        load_stage(s, s * BK);
        asm volatile("cp.async.commit_group;" ::: "memory");
    }

    float acc[2][8][4];
#pragma unroll
    for (int mt = 0; mt < 2; ++mt)
#pragma unroll
        for (int nt = 0; nt < 8; ++nt)
#pragma unroll
            for (int i = 0; i < 4; ++i) acc[mt][nt][i] = 0.f;

    const int g = lane >> 2;                 // group (row) id
    const int q = lane & 3;                  // quad id
    const float* Aw = As + (wm * 32 + g) * LDA;   // warp's 32 m-rows
    const float* Bw = Bs + (wn * 64 + g) * LDA;   // warp's 64 n-rows (expert)

#pragma unroll 1
    for (int kt = 0; kt < KT; ++kt) {
        asm volatile("cp.async.wait_group %0;" :: "n"(STAGES - 2) : "memory");
        __syncthreads();

        const int pf = kt + STAGES - 1;
        if (pf < KT) load_stage(pf % STAGES, pf * BK);
        asm volatile("cp.async.commit_group;" ::: "memory");

        const int cur = kt % STAGES;
        const float* Ac = Aw + cur * A_STG;
        const float* Bc = Bw + cur * B_STG;

        // Two halves; each half's float4 carries 2 k-steps of fragment data.
        // Thread quad q owns global cols {8q+2ks, 8q+2ks+1} (same map A & B).
#pragma unroll
        for (int h2 = 0; h2 < 2; ++h2) {
            const int co = 8 * q + 4 * h2;           // 16B aligned
            float4 al[2], ah[2];                     // A rows g, g+8 per mt
#pragma unroll
            for (int mt = 0; mt < 2; ++mt) {
                const float* p = Ac + mt * 16 * LDA + co;
                al[mt] = *reinterpret_cast<const float4*>(p);
                ah[mt] = *reinterpret_cast<const float4*>(p + 8 * LDA);
            }
            // B in two groups of 4 to bound live registers (~115 total)
#pragma unroll
            for (int ng = 0; ng < 2; ++ng) {
                float4 bv[4];
#pragma unroll
                for (int j = 0; j < 4; ++j)
                    bv[j] = *reinterpret_cast<const float4*>(
                                Bc + ((ng * 4 + j) * 8) * LDA + co);
                // pass 1: ks = 2*h2   (x/y lanes) — 8 independent acc chains
#pragma unroll
                for (int mt = 0; mt < 2; ++mt)
#pragma unroll
                    for (int j = 0; j < 4; ++j)
                        mma_tf32(acc[mt][ng * 4 + j],
                                 fu(al[mt].x), fu(ah[mt].x),
                                 fu(al[mt].y), fu(ah[mt].y),
                                 fu(bv[j].x),  fu(bv[j].y));
                // pass 2: ks = 2*h2+1 (z/w lanes)
#pragma unroll
                for (int mt = 0; mt < 2; ++mt)
#pragma unroll
                    for (int j = 0; j < 4; ++j)
                        mma_tf32(acc[mt][ng * 4 + j],
                                 fu(al[mt].z), fu(ah[mt].z),
                                 fu(al[mt].w), fu(ah[mt].w),
                                 fu(bv[j].z),  fu(bv[j].w));
            }
        }
    }

    // ---- epilogue: ||.||_2 over this warp's 64 n-cols (one expert) --------
    const int e = blockIdx.x * (BN / 64) + wn;
#pragma unroll
    for (int mt = 0; mt < 2; ++mt) {
        float s0 = 0.f, s1 = 0.f;
#pragma unroll
        for (int nt = 0; nt < 8; ++nt) {
            s0 = fmaf(acc[mt][nt][0], acc[mt][nt][0], s0);
            s0 = fmaf(acc[mt][nt][1], acc[mt][nt][1], s0);
            s1 = fmaf(acc[mt][nt][2], acc[mt][nt][2], s1);
            s1 = fmaf(acc[mt][nt][3], acc[mt][nt][3], s1);
        }
        s0 += __shfl_xor_sync(0xffffffffu, s0, 1);
        s0 += __shfl_xor_sync(0xffffffffu, s0, 2);
        s1 += __shfl_xor_sync(0xffffffffu, s1, 1);
        s1 += __shfl_xor_sync(0xffffffffu, s1, 2);
        if ((lane & 3) == 0) {
            const int row = m_base + wm * 32 + mt * 16 + g;
            out[(size_t)row * EDIM + e]       = sqrtf(s0);
            out[(size_t)(row + 8) * EDIM + e] = sqrtf(s1);
        }
    }
}

// ---------------------------------------------------------------------------
extern "C" void kernel_launch(void* const* d_in, const int* in_sizes, int n_in,
                              void* d_out, int out_size) {
    (void)in_sizes; (void)n_in; (void)out_size;
    const float* x = (const float*)d_in[0];   // [8192, 4096]
    const float* w = (const float*)d_in[1];   // [16, 64, 4096] == [1024, 4096]
    float* out = (float*)d_out;               // [8192, 16]

    prep_round_x<<<(BDIM * DDIM / 4) / 256, 256>>>((const float4*)x);
    prep_round_w<<<(NTOT * DDIM / 4) / 256, 256>>>((const float4*)w);

    cudaFuncSetAttribute(router_kernel,
                         cudaFuncAttributeMaxDynamicSharedMemorySize, SMEM_BYTES);
    router_kernel<<<dim3(NTOT / BN, BDIM / BM), 512, SMEM_BYTES>>>(out);
}

// round 9
// speedup vs baseline: 2.1566x; 2.1566x over previous
#include <cuda_runtime.h>
#include <cstdint>

// ---------------------------------------------------------------------------
// Router: r[b,e] = || W[e] @ x[b] ||_2
//   x: [8192,4096] f32, W: [16,64,4096] f32, out: [8192,16] f32
// GEMM C = X @ W^T via mma.sync.m16n8k16.bf16 (base sm_103 target).
// R9 vs R7/R8: R6..R8 were invariant (~480-500us GEMM) across instruction
// count and warp count -> bound by the legacy-HMMA instruction path
// (~144 TF/s measured). bf16 m16n8k16 doubles MACs/instruction -> halve MMA
// count. Inputs pre-rounded to bf16 RN (unbiased); tf32 gave 3.8e-5,
// bf16 roundoff is exactly 4x coarser -> predicted rel_err ~1.5e-4 << 1e-3.
// ---------------------------------------------------------------------------

#define BDIM   8192
#define DDIM   4096
#define EDIM   16
#define NTOT   1024
#define BM     128
#define BN     256
#define BK     64                      /* bf16 cols per stage = 128B/row    */
#define STAGES 3
#define KT     (DDIM / BK)             /* 64 mainloop iterations            */
#define RSB    192                     /* smem row stride bytes (=64 mod 128:
                                          conflict-free 16B phases)          */
#define A_BYTES (BM * RSB)             /* 24576 */
#define B_BYTES (BN * RSB)             /* 49152 */
#define STG_BYTES (A_BYTES + B_BYTES)  /* 73728 */
#define SMEM_BYTES (STAGES * STG_BYTES)/* 221184 */

// bf16 scratch copies of the inputs (module-scope __device__ = legal scratch)
__device__ uint4 g_xb[(size_t)BDIM * DDIM / 8];   // 67 MB
__device__ uint4 g_wb[(size_t)NTOT * DDIM / 8];   //  8.4 MB

__device__ __forceinline__ void mma_bf16(float c[4],
                                         uint32_t a0, uint32_t a1,
                                         uint32_t a2, uint32_t a3,
                                         uint32_t b0, uint32_t b1) {
    asm volatile(
        "mma.sync.aligned.m16n8k16.row.col.f32.bf16.bf16.f32 "
        "{%0,%1,%2,%3}, {%4,%5,%6,%7}, {%8,%9}, {%0,%1,%2,%3};"
        : "+f"(c[0]), "+f"(c[1]), "+f"(c[2]), "+f"(c[3])
        : "r"(a0), "r"(a1), "r"(a2), "r"(a3), "r"(b0), "r"(b1));
}

__device__ __forceinline__ void cp16(uint32_t dst, const void* src) {
    asm volatile("cp.async.cg.shared.global [%0], [%1], 16;"
                 :: "r"(dst), "l"(src) : "memory");
}

__device__ __forceinline__ uint32_t pack_bf16x2(float lo, float hi) {
    uint32_t r;
    asm("cvt.rn.bf16x2.f32 %0, %1, %2;" : "=r"(r) : "f"(hi), "f"(lo));
    return r;
}

// ---------------------------------------------------------------------------
// Prep: f32 -> bf16 (RN, unbiased). Each thread converts 8 floats -> 1 uint4.
// ---------------------------------------------------------------------------
__global__ void prep_x(const float4* __restrict__ src) {
    size_t i = (size_t)blockIdx.x * blockDim.x + threadIdx.x;
    float4 v0 = src[2 * i], v1 = src[2 * i + 1];
    uint4 o;
    o.x = pack_bf16x2(v0.x, v0.y);
    o.y = pack_bf16x2(v0.z, v0.w);
    o.z = pack_bf16x2(v1.x, v1.y);
    o.w = pack_bf16x2(v1.z, v1.w);
    g_xb[i] = o;
}

__global__ void prep_w(const float4* __restrict__ src) {
    size_t i = (size_t)blockIdx.x * blockDim.x + threadIdx.x;
    float4 v0 = src[2 * i], v1 = src[2 * i + 1];
    uint4 o;
    o.x = pack_bf16x2(v0.x, v0.y);
    o.y = pack_bf16x2(v0.z, v0.w);
    o.z = pack_bf16x2(v1.x, v1.y);
    o.w = pack_bf16x2(v1.z, v1.w);
    g_wb[i] = o;
}

// ---------------------------------------------------------------------------
// grid = (NTOT/BN = 4, BDIM/BM = 64), n fastest (A reused via L2).
// 8 warps: 2(m) x 4(n); warp tile 64x64 = one expert per warp.
// k-slot remap per 32-col chunk: physical bf16 cols [8q..8q+7] serve MMA
// instances {0,1} x slots {2q,2q+1,2q+8,2q+9} (same map for A and B), so one
// LDS.128 per row feeds two m16n8k16 MMAs.
// ---------------------------------------------------------------------------
__global__ __launch_bounds__(256, 1)
void router_kernel(float* __restrict__ out) {
    extern __shared__ char smem[];

    const int tid  = threadIdx.x;
    const int lane = tid & 31;
    const int wid  = tid >> 5;
    const int wm   = wid & 1;
    const int wn   = wid >> 1;

    const int m_base = blockIdx.y * BM;
    const int n_base = blockIdx.x * BN;

    // ---- cp.async producer: thread -> (row = tid/8, 16B chunk = tid%8) ----
    const int lrow = tid >> 3;               // 0..31
    const int lch  = tid & 7;                // 0..7
    const char* gA = (const char*)g_xb
                   + ((size_t)(m_base + lrow) * DDIM + lch * 8) * 2;
    const char* gB = (const char*)g_wb
                   + ((size_t)(n_base + lrow) * DDIM + lch * 8) * 2;
    const uint32_t sbase = (uint32_t)__cvta_generic_to_shared(smem);
    const uint32_t sA0 = sbase + (uint32_t)(lrow * RSB + lch * 16);
    const uint32_t sB0 = sA0 + A_BYTES;

    auto load_stage = [&](int s, int kb /*bf16 col offset*/) {
        const uint32_t so = (uint32_t)(s * STG_BYTES);
        const char* ga = gA + (size_t)kb * 2;
#pragma unroll
        for (int p = 0; p < BM / 32; ++p)
            cp16(sA0 + so + (uint32_t)(p * 32 * RSB), ga + (size_t)(p * 32) * DDIM * 2);
        const char* gb = gB + (size_t)kb * 2;
#pragma unroll
        for (int p = 0; p < BN / 32; ++p)
            cp16(sB0 + so + (uint32_t)(p * 32 * RSB), gb + (size_t)(p * 32) * DDIM * 2);
    };

#pragma unroll
    for (int s = 0; s < STAGES - 1; ++s) {
        load_stage(s, s * BK);
        asm volatile("cp.async.commit_group;" ::: "memory");
    }

    float acc[4][8][4];
#pragma unroll
    for (int mt = 0; mt < 4; ++mt)
#pragma unroll
        for (int nt = 0; nt < 8; ++nt)
#pragma unroll
            for (int i = 0; i < 4; ++i) acc[mt][nt][i] = 0.f;

    const int g = lane >> 2;                 // group (row) id
    const int q = lane & 3;                  // quad id
    const char* Aw = smem + (wm * 64 + g) * RSB + q * 16;        // A rows
    const char* Bw = smem + A_BYTES + (wn * 64 + g) * RSB + q * 16;

#pragma unroll 1
    for (int kt = 0; kt < KT; ++kt) {
        asm volatile("cp.async.wait_group %0;" :: "n"(STAGES - 2) : "memory");
        __syncthreads();

        const int pf = kt + STAGES - 1;
        if (pf < KT) load_stage(pf % STAGES, pf * BK);
        asm volatile("cp.async.commit_group;" ::: "memory");

        const int cur = kt % STAGES;
        const char* Ac = Aw + cur * STG_BYTES;
        const char* Bc = Bw + cur * STG_BYTES;

#pragma unroll
        for (int c2 = 0; c2 < 2; ++c2) {     // two 32-col chunks per stage
            const int co = c2 * 64;          // byte offset within row data
            uint4 al[4], ah[4];              // A rows g, g+8 per mt
#pragma unroll
            for (int mt = 0; mt < 4; ++mt) {
                const char* p = Ac + mt * 16 * RSB + co;
                al[mt] = *reinterpret_cast<const uint4*>(p);
                ah[mt] = *reinterpret_cast<const uint4*>(p + 8 * RSB);
            }
            uint4 bv[8];
#pragma unroll
            for (int nt = 0; nt < 8; ++nt)
                bv[nt] = *reinterpret_cast<const uint4*>(Bc + nt * 8 * RSB + co);

            // instance 0: fragment halves .x/.y — 32 independent acc chains
#pragma unroll
            for (int mt = 0; mt < 4; ++mt)
#pragma unroll
                for (int nt = 0; nt < 8; ++nt)
                    mma_bf16(acc[mt][nt],
                             al[mt].x, ah[mt].x, al[mt].y, ah[mt].y,
                             bv[nt].x, bv[nt].y);
            // instance 1: fragment halves .z/.w
#pragma unroll
            for (int mt = 0; mt < 4; ++mt)
#pragma unroll
                for (int nt = 0; nt < 8; ++nt)
                    mma_bf16(acc[mt][nt],
                             al[mt].z, ah[mt].z, al[mt].w, ah[mt].w,
                             bv[nt].z, bv[nt].w);
        }
    }

    // ---- epilogue: ||.||_2 over this warp's 64 n-cols (one expert) --------
    const int e = blockIdx.x * (BN / 64) + wn;
#pragma unroll
    for (int mt = 0; mt < 4; ++mt) {
        float s0 = 0.f, s1 = 0.f;
#pragma unroll
        for (int nt = 0; nt < 8; ++nt) {
            s0 = fmaf(acc[mt][nt][0], acc[mt][nt][0], s0);
            s0 = fmaf(acc[mt][nt][1], acc[mt][nt][1], s0);
            s1 = fmaf(acc[mt][nt][2], acc[mt][nt][2], s1);
            s1 = fmaf(acc[mt][nt][3], acc[mt][nt][3], s1);
        }
        s0 += __shfl_xor_sync(0xffffffffu, s0, 1);
        s0 += __shfl_xor_sync(0xffffffffu, s0, 2);
        s1 += __shfl_xor_sync(0xffffffffu, s1, 1);
        s1 += __shfl_xor_sync(0xffffffffu, s1, 2);
        if ((lane & 3) == 0) {
            const int row = m_base + wm * 64 + mt * 16 + g;
            out[(size_t)row * EDIM + e]       = sqrtf(s0);
            out[(size_t)(row + 8) * EDIM + e] = sqrtf(s1);
        }
    }
}

// ---------------------------------------------------------------------------
extern "C" void kernel_launch(void* const* d_in, const int* in_sizes, int n_in,
                              void* d_out, int out_size) {
    (void)in_sizes; (void)n_in; (void)out_size;
    const float* x = (const float*)d_in[0];   // [8192, 4096]
    const float* w = (const float*)d_in[1];   // [16, 64, 4096]
    float* out = (float*)d_out;               // [8192, 16]

    prep_x<<<(BDIM * (size_t)DDIM / 8) / 256, 256>>>((const float4*)x);
    prep_w<<<(NTOT * (size_t)DDIM / 8) / 256, 256>>>((const float4*)w);

    cudaFuncSetAttribute(router_kernel,
                         cudaFuncAttributeMaxDynamicSharedMemorySize, SMEM_BYTES);
    router_kernel<<<dim3(NTOT / BN, BDIM / BM), 256, SMEM_BYTES>>>(out);
}